// round 5
// baseline (speedup 1.0000x reference)
#include <cuda_runtime.h>
#include <cuda_bf16.h>
#include <cstdint>

#define NROWS 8192
#define DDIM  256
#define KSEL  64
#define SLOT_CAP 128
#define CAND_CAP 1024
#define AMB_CAP  64

__device__ __constant__ float kNEG = -1.0e9f;

// ---------------- scratch (static device globals; no runtime alloc) -------------
__device__ float g_Q[(size_t)NROWS * DDIM];
__device__ float g_K[(size_t)NROWS * DDIM];
__device__ float g_V[(size_t)NROWS * DDIM];
__device__ float g_S[(size_t)NROWS * NROWS];          // 256 MB score matrix
__device__ __align__(16) __nv_bfloat16 g_Qh[(size_t)NROWS * DDIM];
__device__ __align__(16) __nv_bfloat16 g_Ql[(size_t)NROWS * DDIM];
__device__ __align__(16) __nv_bfloat16 g_Kh[(size_t)NROWS * DDIM];
__device__ __align__(16) __nv_bfloat16 g_Kl[(size_t)NROWS * DDIM];
__device__ int   g_idx[(size_t)NROWS * SLOT_CAP];
__device__ float g_e[(size_t)NROWS * SLOT_CAP];
__device__ int   g_cnt[NROWS];
__device__ float g_sum[NROWS];

// ---------------- generic helpers ----------------
typedef unsigned long long ull;

__device__ __forceinline__ ull pack2(float lo, float hi) {
    ull r;
    asm("mov.b64 %0, {%1, %2};" : "=l"(r) : "r"(__float_as_uint(lo)), "r"(__float_as_uint(hi)));
    return r;
}
__device__ __forceinline__ void unpack2(float& lo, float& hi, ull v) {
    unsigned a, b;
    asm("mov.b64 {%0, %1}, %2;" : "=r"(a), "=r"(b) : "l"(v));
    lo = __uint_as_float(a); hi = __uint_as_float(b);
}
__device__ __forceinline__ void fma2(ull& d, ull a, ull b) {
    asm("fma.rn.f32x2 %0, %1, %2, %3;" : "=l"(d) : "l"(a), "l"(b), "l"(d));
}
__device__ __forceinline__ unsigned f2u(float f) {
    unsigned b = __float_as_uint(f);
    return (b & 0x80000000u) ? ~b : (b | 0x80000000u);
}
__device__ __forceinline__ float u2f(unsigned x) {
    unsigned b = (x & 0x80000000u) ? (x ^ 0x80000000u) : ~x;
    return __uint_as_float(b);
}
__device__ __forceinline__ uint32_t smem_u32(const void* p) {
    uint32_t a;
    asm("{ .reg .u64 t; cvta.to.shared.u64 t, %1; cvt.u32.u64 %0, t; }" : "=r"(a) : "l"(p));
    return a;
}

// ---------------- baseline-PTX async copy + tensor-core macros ----------------
#define CP_ASYNC16(dst, src) \
    asm volatile("cp.async.cg.shared.global [%0], [%1], 16;" :: "r"(dst), "l"(src) : "memory")
#define CP_COMMIT() asm volatile("cp.async.commit_group;" ::: "memory")
#define CP_WAIT(n)  asm volatile("cp.async.wait_group %0;" :: "n"(n) : "memory")

#define LDSM_X4(r, addr) \
    asm volatile("ldmatrix.sync.aligned.m8n8.x4.shared.b16 {%0,%1,%2,%3}, [%4];" \
        : "=r"((r)[0]), "=r"((r)[1]), "=r"((r)[2]), "=r"((r)[3]) : "r"(addr))

#define MMA16816(d, a, b0, b1) \
    asm volatile("mma.sync.aligned.m16n8k16.row.col.f32.bf16.bf16.f32 " \
        "{%0,%1,%2,%3}, {%4,%5,%6,%7}, {%8,%9}, {%0,%1,%2,%3};" \
        : "+f"((d)[0]), "+f"((d)[1]), "+f"((d)[2]), "+f"((d)[3]) \
        : "r"((a)[0]), "r"((a)[1]), "r"((a)[2]), "r"((a)[3]), "r"(b0), "r"(b1))

#define SW128(off) ((off) ^ (((off) >> 3) & 0x70))

// ---------------- block reductions (256 threads, 8 warps) ----------------
__device__ __forceinline__ int blockSumI(int v, int* buf, int tid) {
    #pragma unroll
    for (int o = 16; o; o >>= 1) v += __shfl_down_sync(0xffffffffu, v, o);
    if ((tid & 31) == 0) buf[tid >> 5] = v;
    __syncthreads();
    if (tid < 32) {
        int t = (tid < 8) ? buf[tid] : 0;
        #pragma unroll
        for (int o = 4; o; o >>= 1) t += __shfl_down_sync(0xffffffffu, t, o);
        if (tid == 0) buf[0] = t;
    }
    __syncthreads();
    int r = buf[0];
    __syncthreads();
    return r;
}
__device__ __forceinline__ float blockSumF(float v, float* buf, int tid) {
    #pragma unroll
    for (int o = 16; o; o >>= 1) v += __shfl_down_sync(0xffffffffu, v, o);
    if ((tid & 31) == 0) buf[tid >> 5] = v;
    __syncthreads();
    if (tid < 32) {
        float t = (tid < 8) ? buf[tid] : 0.f;
        #pragma unroll
        for (int o = 4; o; o >>= 1) t += __shfl_down_sync(0xffffffffu, t, o);
        if (tid == 0) buf[0] = t;
    }
    __syncthreads();
    float r = buf[0];
    __syncthreads();
    return r;
}
__device__ __forceinline__ unsigned blockMaxU(unsigned v, unsigned* buf, int tid) {
    #pragma unroll
    for (int o = 16; o; o >>= 1) v = max(v, __shfl_down_sync(0xffffffffu, v, o));
    if ((tid & 31) == 0) buf[tid >> 5] = v;
    __syncthreads();
    if (tid < 32) {
        unsigned t = (tid < 8) ? buf[tid] : 0u;
        #pragma unroll
        for (int o = 4; o; o >>= 1) t = max(t, __shfl_down_sync(0xffffffffu, t, o));
        if (tid == 0) buf[0] = t;
    }
    __syncthreads();
    unsigned r = buf[0];
    __syncthreads();
    return r;
}

// ---------------- FFMA NT-GEMM tile core (for QKV; 128x128, BK=16) --------------
__device__ __forceinline__ void gemm_tile_nt(
    const float* __restrict__ A, const float* __restrict__ B,
    int Kd, int row0, int col0,
    float (*As)[128], float (*Bs)[128], ull acc[8][4])
{
    const int tid = threadIdx.x;
    const int tx = tid & 15, ty = tid >> 4;

    for (int kc = 0; kc < Kd; kc += 16) {
        #pragma unroll
        for (int l = 0; l < 2; l++) {
            int flat = tid + (l << 8);
            int r  = flat >> 2;
            int kq = (flat & 3) << 2;
            float4 va = *(const float4*)(A + (size_t)(row0 + r) * Kd + kc + kq);
            As[kq + 0][r] = va.x; As[kq + 1][r] = va.y;
            As[kq + 2][r] = va.z; As[kq + 3][r] = va.w;
            float4 vb = *(const float4*)(B + (size_t)(col0 + r) * Kd + kc + kq);
            Bs[kq + 0][r] = vb.x; Bs[kq + 1][r] = vb.y;
            Bs[kq + 2][r] = vb.z; Bs[kq + 3][r] = vb.w;
        }
        __syncthreads();
        #pragma unroll
        for (int kk = 0; kk < 16; kk++) {
            float4 a0 = *(const float4*)(&As[kk][ty * 4]);
            float4 a1 = *(const float4*)(&As[kk][ty * 4 + 64]);
            float4 b0 = *(const float4*)(&Bs[kk][tx * 4]);
            float4 b1 = *(const float4*)(&Bs[kk][tx * 4 + 64]);
            ull bb0 = pack2(b0.x, b0.y), bb1 = pack2(b0.z, b0.w);
            ull bb2 = pack2(b1.x, b1.y), bb3 = pack2(b1.z, b1.w);
            float av[8] = {a0.x, a0.y, a0.z, a0.w, a1.x, a1.y, a1.z, a1.w};
            #pragma unroll
            for (int i = 0; i < 8; i++) {
                ull aa = pack2(av[i], av[i]);
                fma2(acc[i][0], aa, bb0);
                fma2(acc[i][1], aa, bb1);
                fma2(acc[i][2], aa, bb2);
                fma2(acc[i][3], aa, bb3);
            }
        }
        __syncthreads();
    }
}

// ---------------- K1: QKV projections (C = X @ W^T + b) ----------------
__global__ __launch_bounds__(256, 2)
void qkv_kernel(const float* __restrict__ X, const float* __restrict__ W,
                const float* __restrict__ bias, int sel)
{
    __shared__ float As[16][128];
    __shared__ float Bs[16][128];
    ull acc[8][4];
    #pragma unroll
    for (int i = 0; i < 8; i++)
        #pragma unroll
        for (int j = 0; j < 4; j++) acc[i][j] = 0ull;

    int row0 = blockIdx.y * 128, col0 = blockIdx.x * 128;
    gemm_tile_nt(X, W, DDIM, row0, col0, As, Bs, acc);

    float* C = (sel == 0) ? g_Q : (sel == 1) ? g_K : g_V;
    const int tid = threadIdx.x, tx = tid & 15, ty = tid >> 4;
    const int gc0 = col0 + tx * 4, gc1 = gc0 + 64;
    float4 b0 = *(const float4*)&bias[gc0];
    float4 b1 = *(const float4*)&bias[gc1];

    #pragma unroll
    for (int i = 0; i < 8; i++) {
        int grow = row0 + ty * 4 + ((i < 4) ? i : 60 + i);
        float o[8];
        unpack2(o[0], o[1], acc[i][0]);
        unpack2(o[2], o[3], acc[i][1]);
        unpack2(o[4], o[5], acc[i][2]);
        unpack2(o[6], o[7], acc[i][3]);
        o[0] += b0.x; o[1] += b0.y; o[2] += b0.z; o[3] += b0.w;
        o[4] += b1.x; o[5] += b1.y; o[6] += b1.z; o[7] += b1.w;
        *(float4*)&C[(size_t)grow * DDIM + gc0] = make_float4(o[0], o[1], o[2], o[3]);
        *(float4*)&C[(size_t)grow * DDIM + gc1] = make_float4(o[4], o[5], o[6], o[7]);
    }
}

// ---------------- K1b: split Q,K into bf16 hi/lo ----------------
__global__ __launch_bounds__(256)
void split_kernel()
{
    const int total = NROWS * DDIM / 4;
    for (int idx = blockIdx.x * blockDim.x + threadIdx.x; idx < total;
         idx += gridDim.x * blockDim.x) {
        {
            float4 q = ((const float4*)g_Q)[idx];
            __nv_bfloat16 h0 = __float2bfloat16(q.x), h1 = __float2bfloat16(q.y);
            __nv_bfloat16 h2 = __float2bfloat16(q.z), h3 = __float2bfloat16(q.w);
            ((__nv_bfloat162*)g_Qh)[idx * 2]     = __nv_bfloat162(h0, h1);
            ((__nv_bfloat162*)g_Qh)[idx * 2 + 1] = __nv_bfloat162(h2, h3);
            ((__nv_bfloat162*)g_Ql)[idx * 2]     = __nv_bfloat162(
                __float2bfloat16(q.x - __bfloat162float(h0)),
                __float2bfloat16(q.y - __bfloat162float(h1)));
            ((__nv_bfloat162*)g_Ql)[idx * 2 + 1] = __nv_bfloat162(
                __float2bfloat16(q.z - __bfloat162float(h2)),
                __float2bfloat16(q.w - __bfloat162float(h3)));
        }
        {
            float4 q = ((const float4*)g_K)[idx];
            __nv_bfloat16 h0 = __float2bfloat16(q.x), h1 = __float2bfloat16(q.y);
            __nv_bfloat16 h2 = __float2bfloat16(q.z), h3 = __float2bfloat16(q.w);
            ((__nv_bfloat162*)g_Kh)[idx * 2]     = __nv_bfloat162(h0, h1);
            ((__nv_bfloat162*)g_Kh)[idx * 2 + 1] = __nv_bfloat162(h2, h3);
            ((__nv_bfloat162*)g_Kl)[idx * 2]     = __nv_bfloat162(
                __float2bfloat16(q.x - __bfloat162float(h0)),
                __float2bfloat16(q.y - __bfloat162float(h1)));
            ((__nv_bfloat162*)g_Kl)[idx * 2 + 1] = __nv_bfloat162(
                __float2bfloat16(q.z - __bfloat162float(h2)),
                __float2bfloat16(q.w - __bfloat162float(h3)));
        }
    }
}

// ---------------- K2: HMMA (mma.sync bf16) score GEMM ----------------
#define SM_A0 0
#define SM_B0 16384
#define SM_A1 32768
#define SM_B1 49152
#define SM_SCORE_TOTAL 65536
#define NCHUNK 12

__device__ __forceinline__ void issue_chunk(uint32_t sb, int c, int buf,
                                            int row0, int col0, int tid)
{
    const int p = c >> 2;
    const __nv_bfloat16* __restrict__ A = (p == 2) ? g_Ql : g_Qh;
    const __nv_bfloat16* __restrict__ B = (p == 1) ? g_Kl : g_Kh;
    const int kb = (c & 3) * 128;
    const uint32_t da = sb + (buf ? SM_A1 : SM_A0);
    const uint32_t db = sb + (buf ? SM_B1 : SM_B0);

    #pragma unroll
    for (int i = 0; i < 4; i++) {
        int f = tid + i * 256;
        int row = f >> 3;
        int chk = (f & 7) * 16;
        uint32_t off = SW128((uint32_t)(row * 128 + chk));
        const char* ga = (const char*)(A + (size_t)(row0 + row) * DDIM) + kb + chk;
        CP_ASYNC16(da + off, ga);
        const char* gb = (const char*)(B + (size_t)(col0 + row) * DDIM) + kb + chk;
        CP_ASYNC16(db + off, gb);
    }
    CP_COMMIT();
}

__global__ __launch_bounds__(256)
void score_mma_kernel(const float* __restrict__ temp)
{
    extern __shared__ char smem[];
    const uint32_t sb = smem_u32(smem);
    const int tid = threadIdx.x, lane = tid & 31, wid = tid >> 5;
    const int wm = wid & 3, wn = wid >> 2;
    const int row0 = blockIdx.y * 128, col0 = blockIdx.x * 128;

    float acc[2][8][4];
    #pragma unroll
    for (int i = 0; i < 2; i++)
        #pragma unroll
        for (int j = 0; j < 8; j++)
            #pragma unroll
            for (int q = 0; q < 4; q++) acc[i][j][q] = 0.f;

    issue_chunk(sb, 0, 0, row0, col0, tid);

    for (int c = 0; c < NCHUNK; c++) {
        if (c + 1 < NCHUNK) { issue_chunk(sb, c + 1, (c + 1) & 1, row0, col0, tid); CP_WAIT(1); }
        else                { CP_WAIT(0); }
        __syncthreads();

        const uint32_t ab = sb + ((c & 1) ? SM_A1 : SM_A0);
        const uint32_t bb = sb + ((c & 1) ? SM_B1 : SM_B0);

        #pragma unroll
        for (int ks = 0; ks < 4; ks++) {
            uint32_t ar[2][4], br[4][4];
            #pragma unroll
            for (int mt = 0; mt < 2; mt++) {
                int row = wm * 32 + mt * 16 + (lane & 15);
                int kby = ks * 32 + ((lane >> 4) << 4);
                uint32_t addr = ab + SW128((uint32_t)(row * 128 + kby));
                LDSM_X4(ar[mt], addr);
            }
            #pragma unroll
            for (int pt = 0; pt < 4; pt++) {
                int n   = wn * 64 + pt * 16 + (lane & 7) + ((lane >> 4) << 3);
                int kby = ks * 32 + (((lane >> 3) & 1) << 4);
                uint32_t addr = bb + SW128((uint32_t)(n * 128 + kby));
                LDSM_X4(br[pt], addr);
            }
            #pragma unroll
            for (int mt = 0; mt < 2; mt++)
                #pragma unroll
                for (int pt = 0; pt < 4; pt++) {
                    MMA16816(acc[mt][2 * pt],     ar[mt], br[pt][0], br[pt][1]);
                    MMA16816(acc[mt][2 * pt + 1], ar[mt], br[pt][2], br[pt][3]);
                }
        }
        __syncthreads();
    }

    const float scale = 1.0f / (__ldg(temp) * 16.0f);
    #pragma unroll
    for (int mt = 0; mt < 2; mt++) {
        const int r0g = row0 + wm * 32 + mt * 16 + (lane >> 2);
        const int r1g = r0g + 8;
        #pragma unroll
        for (int nt = 0; nt < 8; nt++) {
            const int gc = col0 + wn * 64 + nt * 8 + (lane & 3) * 2;
            float2 v0, v1;
            v0.x = (r0g == gc)     ? kNEG : acc[mt][nt][0] * scale;
            v0.y = (r0g == gc + 1) ? kNEG : acc[mt][nt][1] * scale;
            v1.x = (r1g == gc)     ? kNEG : acc[mt][nt][2] * scale;
            v1.y = (r1g == gc + 1) ? kNEG : acc[mt][nt][3] * scale;
            *(float2*)&g_S[(size_t)r0g * NROWS + gc] = v0;
            *(float2*)&g_S[(size_t)r1g * NROWS + gc] = v1;
        }
    }
}

// ---------------- K3: top-64 with certified selection ----------------
// Approx scores select everything outside a +-EPS band around the approx 64th
// value; band entries ("ambiguous") are re-scored with exact fp32 dots when the
// selection actually depends on them. Deterministic slot assignment via scan.
__global__ __launch_bounds__(256)
void topk_kernel(const float* __restrict__ temp)
{
    const int row = blockIdx.x;
    const int tid = threadIdx.x;
    const float* __restrict__ srow = g_S + (size_t)row * NROWS;

    unsigned u[32];
    #pragma unroll
    for (int j = 0; j < 32; j++) u[j] = f2u(srow[j * 256 + tid]);

    __shared__ int      red_i[8];
    __shared__ float    red_f[8];
    __shared__ unsigned red_u[8];
    __shared__ unsigned cand[CAND_CAP];
    __shared__ int      ambCol[AMB_CAP];
    __shared__ float    ambVal[AMB_CAP];
    __shared__ unsigned char ambKeep[AMB_CAP];
    __shared__ int      s_ccnt, s_amb, s_total;
    __shared__ int      scan_w[8];

    // row max (approx; softmax shift, cancels)
    unsigned mu = 0;
    #pragma unroll
    for (int j = 0; j < 32; j++) mu = max(mu, u[j]);
    mu = blockMaxU(mu, red_u, tid);
    const float m = u2f(mu);

    // ---- bisection for the bit-exact 64th-largest approx value ----
    unsigned prefix = 0;
    for (int bit = 31; bit >= 24; bit--) {
        unsigned t = prefix | (1u << bit);
        int c = 0;
        #pragma unroll
        for (int j = 0; j < 32; j++) c += (u[j] >= t);
        if (blockSumI(c, red_i, tid) >= KSEL) prefix = t;
    }
    const unsigned P = prefix >> 24;

    int ch = 0;
    #pragma unroll
    for (int j = 0; j < 32; j++) ch += ((u[j] >> 24) > P);
    const int c_hi = blockSumI(ch, red_i, tid);
    const int rem = KSEL - c_hi;

    if (tid == 0) s_ccnt = 0;
    __syncthreads();
    #pragma unroll
    for (int j = 0; j < 32; j++) {
        if ((u[j] >> 24) == P) {
            int p = atomicAdd(&s_ccnt, 1);
            if (p < CAND_CAP) cand[p] = u[j];
        }
    }
    __syncthreads();
    const int nc = s_ccnt;

    if (nc <= CAND_CAP) {
        for (int bit = 23; bit >= 0; bit--) {
            unsigned t = prefix | (1u << bit);
            int c = 0;
            for (int p = tid; p < nc; p += 256) c += (cand[p] >= t);
            if (blockSumI(c, red_i, tid) >= rem) prefix = t;
        }
    } else {
        for (int bit = 23; bit >= 0; bit--) {
            unsigned t = prefix | (1u << bit);
            int c = 0;
            #pragma unroll
            for (int j = 0; j < 32; j++) c += (u[j] >= t);
            if (blockSumI(c, red_i, tid) >= KSEL) prefix = t;
        }
    }
    const unsigned thr = prefix;                 // 64th largest approx (bit exact)

    // ---- band classification ----
    const float scale = 1.0f / (__ldg(temp) * 16.0f);
    const float EPS  = 4e-3f * scale;            // >= 2x max approx-score error
    const float s_thr = u2f(thr);
    const float hiB = s_thr + EPS, loB = s_thr - EPS;

    if (tid == 0) s_amb = 0;
    __syncthreads();
    int nhi_loc = 0;
    #pragma unroll
    for (int j = 0; j < 32; j++) {
        float s = u2f(u[j]);
        if (s > hiB) nhi_loc++;
        else if (s >= loB) {
            int p = atomicAdd(&s_amb, 1);
            if (p < AMB_CAP) ambCol[p] = j * 256 + tid;
        }
    }
    const int n_hi = blockSumI(nhi_loc, red_i, tid);
    const int n_amb = min(s_amb, AMB_CAP);
    const int slots = KSEL - n_hi;
    const bool slow = (n_amb != slots);          // block-uniform

    if (slow) {
        // exact fp32 dots for ambiguous cols
        const float* __restrict__ qrow = g_Q + (size_t)row * DDIM;
        const int wid = tid >> 5, lane = tid & 31;
        for (int i = wid; i < n_amb; i += 8) {
            const float* __restrict__ krow = g_K + (size_t)ambCol[i] * DDIM;
            float part = 0.f;
            const int e0 = lane * 8;
            #pragma unroll
            for (int e = 0; e < 8; e += 4) {
                float4 qa = *(const float4*)(qrow + e0 + e);
                float4 ka = *(const float4*)(krow + e0 + e);
                part += qa.x * ka.x + qa.y * ka.y + qa.z * ka.z + qa.w * ka.w;
            }
            #pragma unroll
            for (int o = 16; o; o >>= 1) part += __shfl_down_sync(0xffffffffu, part, o);
            if (lane == 0) ambVal[i] = part * scale;
        }
        __syncthreads();
        if (tid < n_amb) {
            float v = ambVal[tid];
            int cg = 0;
            for (int i = 0; i < n_amb; i++) cg += (ambVal[i] > v);
            ambKeep[tid] = (cg < slots) ? 1 : 0;  // keeps >=-threshold ties
        }
        __syncthreads();
    }

    // ---- per-thread kept decisions (deterministic) ----
    unsigned keepMask = 0;
    int myCnt = 0;
    float lsum = 0.f;
    #pragma unroll
    for (int j = 0; j < 32; j++) {
        float s = u2f(u[j]);
        bool kp;
        if (s > hiB) kp = true;
        else if (s >= loB) {
            if (!slow) kp = true;                // all band entries fit
            else {
                kp = false;
                const int mycol = j * 256 + tid;
                for (int i = 0; i < n_amb; i++)
                    if (ambCol[i] == mycol) { kp = (ambKeep[i] != 0); break; }
            }
        } else kp = false;
        if (kp) { keepMask |= (1u << j); myCnt++; lsum += expf(s - m); }
    }

    // ---- block exclusive scan of myCnt for deterministic slots ----
    {
        const int lane = tid & 31, wid = tid >> 5;
        int sc = myCnt;
        #pragma unroll
        for (int o = 1; o < 32; o <<= 1) {
            int t = __shfl_up_sync(0xffffffffu, sc, o);
            if (lane >= o) sc += t;
        }
        if (lane == 31) scan_w[wid] = sc;
        __syncthreads();
        if (tid == 0) {
            int acc0 = 0;
            for (int i = 0; i < 8; i++) { int t = scan_w[i]; scan_w[i] = acc0; acc0 += t; }
            s_total = acc0;
        }
        __syncthreads();
        int base = scan_w[wid] + sc - myCnt;     // exclusive prefix

        int slot = base;
        #pragma unroll
        for (int j = 0; j < 32; j++) {
            if (keepMask & (1u << j)) {
                if (slot < SLOT_CAP) {
                    g_idx[(size_t)row * SLOT_CAP + slot] = j * 256 + tid;
                    g_e[(size_t)row * SLOT_CAP + slot]   = expf(u2f(u[j]) - m);
                }
                slot++;
            }
        }
    }

    float tot = blockSumF(lsum, red_f, tid);
    if (tid == 0) {
        g_sum[row] = tot;
        g_cnt[row] = min(s_total, SLOT_CAP);
    }
}

// ---------------- K4: out[row] = (sum_j e_j * V[idx_j]) / sum ----------------
__global__ __launch_bounds__(256)
void out_kernel(float* __restrict__ out)
{
    const int row = blockIdx.x;
    const int tid = threadIdx.x;
    __shared__ int   sidx[SLOT_CAP];
    __shared__ float se[SLOT_CAP];
    const int cnt = g_cnt[row];
    if (tid < SLOT_CAP) {
        sidx[tid] = g_idx[(size_t)row * SLOT_CAP + tid];
        se[tid]   = g_e[(size_t)row * SLOT_CAP + tid];
    }
    __syncthreads();
    const float inv = 1.0f / g_sum[row];

    float a0 = 0.f, a1 = 0.f, a2 = 0.f, a3 = 0.f;
    int j = 0;
    for (; j + 4 <= cnt; j += 4) {
        a0 += se[j + 0] * g_V[(size_t)sidx[j + 0] * DDIM + tid];
        a1 += se[j + 1] * g_V[(size_t)sidx[j + 1] * DDIM + tid];
        a2 += se[j + 2] * g_V[(size_t)sidx[j + 2] * DDIM + tid];
        a3 += se[j + 3] * g_V[(size_t)sidx[j + 3] * DDIM + tid];
    }
    for (; j < cnt; j++) a0 += se[j] * g_V[(size_t)sidx[j] * DDIM + tid];

    out[(size_t)row * DDIM + tid] = (a0 + a1 + a2 + a3) * inv;
}

// ---------------- launch ----------------
extern "C" void kernel_launch(void* const* d_in, const int* in_sizes, int n_in,
                              void* d_out, int out_size)
{
    const float* X    = (const float*)d_in[0];
    const float* Wq   = (const float*)d_in[1];
    const float* bq   = (const float*)d_in[2];
    const float* Wk   = (const float*)d_in[3];
    const float* bk   = (const float*)d_in[4];
    const float* Wv   = (const float*)d_in[5];
    const float* bv   = (const float*)d_in[6];
    const float* temp = (const float*)d_in[7];
    float* out = (float*)d_out;

    cudaFuncSetAttribute(score_mma_kernel,
                         cudaFuncAttributeMaxDynamicSharedMemorySize, SM_SCORE_TOTAL);

    dim3 blk(256);
    dim3 gQKV(DDIM / 128, NROWS / 128);
    qkv_kernel<<<gQKV, blk>>>(X, Wq, bq, 0);
    qkv_kernel<<<gQKV, blk>>>(X, Wk, bk, 1);
    qkv_kernel<<<gQKV, blk>>>(X, Wv, bv, 2);

    split_kernel<<<512, 256>>>();

    dim3 gS(NROWS / 128, NROWS / 128);
    score_mma_kernel<<<gS, blk, SM_SCORE_TOTAL>>>(temp);

    topk_kernel<<<NROWS, blk>>>(temp);
    out_kernel<<<NROWS, blk>>>(out);
}

// round 6
// speedup vs baseline: 1.0067x; 1.0067x over previous
#include <cuda_runtime.h>
#include <cuda_bf16.h>
#include <cstdint>

#define NROWS 8192
#define DDIM  256
#define KSEL  64
#define SLOT_CAP 128
#define CAND_CAP 1024
#define AMB_CAP  64

__device__ __constant__ float kNEG = -1.0e9f;

// ---------------- scratch (static device globals; no runtime alloc) -------------
__device__ float g_Q[(size_t)NROWS * DDIM];
__device__ float g_K[(size_t)NROWS * DDIM];
__device__ float g_V[(size_t)NROWS * DDIM];
__device__ float g_S[(size_t)NROWS * NROWS];          // 256 MB score matrix
__device__ __align__(16) __nv_bfloat16 g_Qh[(size_t)NROWS * DDIM];
__device__ __align__(16) __nv_bfloat16 g_Ql[(size_t)NROWS * DDIM];
__device__ __align__(16) __nv_bfloat16 g_Kh[(size_t)NROWS * DDIM];
__device__ __align__(16) __nv_bfloat16 g_Kl[(size_t)NROWS * DDIM];
__device__ int   g_idx[(size_t)NROWS * SLOT_CAP];
__device__ float g_e[(size_t)NROWS * SLOT_CAP];
__device__ int   g_cnt[NROWS];
__device__ float g_sum[NROWS];

// ---------------- generic helpers ----------------
typedef unsigned long long ull;

__device__ __forceinline__ ull pack2(float lo, float hi) {
    ull r;
    asm("mov.b64 %0, {%1, %2};" : "=l"(r) : "r"(__float_as_uint(lo)), "r"(__float_as_uint(hi)));
    return r;
}
__device__ __forceinline__ void unpack2(float& lo, float& hi, ull v) {
    unsigned a, b;
    asm("mov.b64 {%0, %1}, %2;" : "=r"(a), "=r"(b) : "l"(v));
    lo = __uint_as_float(a); hi = __uint_as_float(b);
}
__device__ __forceinline__ void fma2(ull& d, ull a, ull b) {
    asm("fma.rn.f32x2 %0, %1, %2, %3;" : "=l"(d) : "l"(a), "l"(b), "l"(d));
}
__device__ __forceinline__ unsigned f2u(float f) {
    unsigned b = __float_as_uint(f);
    return (b & 0x80000000u) ? ~b : (b | 0x80000000u);
}
__device__ __forceinline__ float u2f(unsigned x) {
    unsigned b = (x & 0x80000000u) ? (x ^ 0x80000000u) : ~x;
    return __uint_as_float(b);
}
__device__ __forceinline__ uint32_t smem_u32(const void* p) {
    uint32_t a;
    asm("{ .reg .u64 t; cvta.to.shared.u64 t, %1; cvt.u32.u64 %0, t; }" : "=r"(a) : "l"(p));
    return a;
}

// ---------------- baseline-PTX async copy + tensor-core macros ----------------
#define CP_ASYNC16(dst, src) \
    asm volatile("cp.async.cg.shared.global [%0], [%1], 16;" :: "r"(dst), "l"(src) : "memory")
#define CP_COMMIT() asm volatile("cp.async.commit_group;" ::: "memory")
#define CP_WAIT(n)  asm volatile("cp.async.wait_group %0;" :: "n"(n) : "memory")

#define LDSM_X4(r, addr) \
    asm volatile("ldmatrix.sync.aligned.m8n8.x4.shared.b16 {%0,%1,%2,%3}, [%4];" \
        : "=r"((r)[0]), "=r"((r)[1]), "=r"((r)[2]), "=r"((r)[3]) : "r"(addr))

#define MMA16816(d, a, b0, b1) \
    asm volatile("mma.sync.aligned.m16n8k16.row.col.f32.bf16.bf16.f32 " \
        "{%0,%1,%2,%3}, {%4,%5,%6,%7}, {%8,%9}, {%0,%1,%2,%3};" \
        : "+f"((d)[0]), "+f"((d)[1]), "+f"((d)[2]), "+f"((d)[3]) \
        : "r"((a)[0]), "r"((a)[1]), "r"((a)[2]), "r"((a)[3]), "r"(b0), "r"(b1))

#define SW128(off) ((off) ^ (((off) >> 3) & 0x70))

// ---------------- block reductions (256 threads, 8 warps) ----------------
__device__ __forceinline__ int blockSumI(int v, int* buf, int tid) {
    #pragma unroll
    for (int o = 16; o; o >>= 1) v += __shfl_down_sync(0xffffffffu, v, o);
    if ((tid & 31) == 0) buf[tid >> 5] = v;
    __syncthreads();
    if (tid < 32) {
        int t = (tid < 8) ? buf[tid] : 0;
        #pragma unroll
        for (int o = 4; o; o >>= 1) t += __shfl_down_sync(0xffffffffu, t, o);
        if (tid == 0) buf[0] = t;
    }
    __syncthreads();
    int r = buf[0];
    __syncthreads();
    return r;
}
__device__ __forceinline__ float blockSumF(float v, float* buf, int tid) {
    #pragma unroll
    for (int o = 16; o; o >>= 1) v += __shfl_down_sync(0xffffffffu, v, o);
    if ((tid & 31) == 0) buf[tid >> 5] = v;
    __syncthreads();
    if (tid < 32) {
        float t = (tid < 8) ? buf[tid] : 0.f;
        #pragma unroll
        for (int o = 4; o; o >>= 1) t += __shfl_down_sync(0xffffffffu, t, o);
        if (tid == 0) buf[0] = t;
    }
    __syncthreads();
    float r = buf[0];
    __syncthreads();
    return r;
}
__device__ __forceinline__ unsigned blockMaxU(unsigned v, unsigned* buf, int tid) {
    #pragma unroll
    for (int o = 16; o; o >>= 1) v = max(v, __shfl_down_sync(0xffffffffu, v, o));
    if ((tid & 31) == 0) buf[tid >> 5] = v;
    __syncthreads();
    if (tid < 32) {
        unsigned t = (tid < 8) ? buf[tid] : 0u;
        #pragma unroll
        for (int o = 4; o; o >>= 1) t = max(t, __shfl_down_sync(0xffffffffu, t, o));
        if (tid == 0) buf[0] = t;
    }
    __syncthreads();
    unsigned r = buf[0];
    __syncthreads();
    return r;
}

// ---------------- FFMA NT-GEMM tile core (for QKV; 128x128, BK=16) --------------
__device__ __forceinline__ void gemm_tile_nt(
    const float* __restrict__ A, const float* __restrict__ B,
    int Kd, int row0, int col0,
    float (*As)[128], float (*Bs)[128], ull acc[8][4])
{
    const int tid = threadIdx.x;
    const int tx = tid & 15, ty = tid >> 4;

    for (int kc = 0; kc < Kd; kc += 16) {
        #pragma unroll
        for (int l = 0; l < 2; l++) {
            int flat = tid + (l << 8);
            int r  = flat >> 2;
            int kq = (flat & 3) << 2;
            float4 va = *(const float4*)(A + (size_t)(row0 + r) * Kd + kc + kq);
            As[kq + 0][r] = va.x; As[kq + 1][r] = va.y;
            As[kq + 2][r] = va.z; As[kq + 3][r] = va.w;
            float4 vb = *(const float4*)(B + (size_t)(col0 + r) * Kd + kc + kq);
            Bs[kq + 0][r] = vb.x; Bs[kq + 1][r] = vb.y;
            Bs[kq + 2][r] = vb.z; Bs[kq + 3][r] = vb.w;
        }
        __syncthreads();
        #pragma unroll
        for (int kk = 0; kk < 16; kk++) {
            float4 a0 = *(const float4*)(&As[kk][ty * 4]);
            float4 a1 = *(const float4*)(&As[kk][ty * 4 + 64]);
            float4 b0 = *(const float4*)(&Bs[kk][tx * 4]);
            float4 b1 = *(const float4*)(&Bs[kk][tx * 4 + 64]);
            ull bb0 = pack2(b0.x, b0.y), bb1 = pack2(b0.z, b0.w);
            ull bb2 = pack2(b1.x, b1.y), bb3 = pack2(b1.z, b1.w);
            float av[8] = {a0.x, a0.y, a0.z, a0.w, a1.x, a1.y, a1.z, a1.w};
            #pragma unroll
            for (int i = 0; i < 8; i++) {
                ull aa = pack2(av[i], av[i]);
                fma2(acc[i][0], aa, bb0);
                fma2(acc[i][1], aa, bb1);
                fma2(acc[i][2], aa, bb2);
                fma2(acc[i][3], aa, bb3);
            }
        }
        __syncthreads();
    }
}

// ---------------- K1: QKV projections (C = X @ W^T + b) ----------------
__global__ __launch_bounds__(256, 2)
void qkv_kernel(const float* __restrict__ X, const float* __restrict__ W,
                const float* __restrict__ bias, int sel)
{
    __shared__ float As[16][128];
    __shared__ float Bs[16][128];
    ull acc[8][4];
    #pragma unroll
    for (int i = 0; i < 8; i++)
        #pragma unroll
        for (int j = 0; j < 4; j++) acc[i][j] = 0ull;

    int row0 = blockIdx.y * 128, col0 = blockIdx.x * 128;
    gemm_tile_nt(X, W, DDIM, row0, col0, As, Bs, acc);

    float* C = (sel == 0) ? g_Q : (sel == 1) ? g_K : g_V;
    const int tid = threadIdx.x, tx = tid & 15, ty = tid >> 4;
    const int gc0 = col0 + tx * 4, gc1 = gc0 + 64;
    float4 b0 = *(const float4*)&bias[gc0];
    float4 b1 = *(const float4*)&bias[gc1];

    #pragma unroll
    for (int i = 0; i < 8; i++) {
        int grow = row0 + ty * 4 + ((i < 4) ? i : 60 + i);
        float o[8];
        unpack2(o[0], o[1], acc[i][0]);
        unpack2(o[2], o[3], acc[i][1]);
        unpack2(o[4], o[5], acc[i][2]);
        unpack2(o[6], o[7], acc[i][3]);
        o[0] += b0.x; o[1] += b0.y; o[2] += b0.z; o[3] += b0.w;
        o[4] += b1.x; o[5] += b1.y; o[6] += b1.z; o[7] += b1.w;
        *(float4*)&C[(size_t)grow * DDIM + gc0] = make_float4(o[0], o[1], o[2], o[3]);
        *(float4*)&C[(size_t)grow * DDIM + gc1] = make_float4(o[4], o[5], o[6], o[7]);
    }
}

// ---------------- K1b: split Q,K into bf16 hi/lo ----------------
__global__ __launch_bounds__(256)
void split_kernel()
{
    const int total = NROWS * DDIM / 4;
    for (int idx = blockIdx.x * blockDim.x + threadIdx.x; idx < total;
         idx += gridDim.x * blockDim.x) {
        {
            float4 q = ((const float4*)g_Q)[idx];
            __nv_bfloat16 h0 = __float2bfloat16(q.x), h1 = __float2bfloat16(q.y);
            __nv_bfloat16 h2 = __float2bfloat16(q.z), h3 = __float2bfloat16(q.w);
            ((__nv_bfloat162*)g_Qh)[idx * 2]     = __nv_bfloat162(h0, h1);
            ((__nv_bfloat162*)g_Qh)[idx * 2 + 1] = __nv_bfloat162(h2, h3);
            ((__nv_bfloat162*)g_Ql)[idx * 2]     = __nv_bfloat162(
                __float2bfloat16(q.x - __bfloat162float(h0)),
                __float2bfloat16(q.y - __bfloat162float(h1)));
            ((__nv_bfloat162*)g_Ql)[idx * 2 + 1] = __nv_bfloat162(
                __float2bfloat16(q.z - __bfloat162float(h2)),
                __float2bfloat16(q.w - __bfloat162float(h3)));
        }
        {
            float4 q = ((const float4*)g_K)[idx];
            __nv_bfloat16 h0 = __float2bfloat16(q.x), h1 = __float2bfloat16(q.y);
            __nv_bfloat16 h2 = __float2bfloat16(q.z), h3 = __float2bfloat16(q.w);
            ((__nv_bfloat162*)g_Kh)[idx * 2]     = __nv_bfloat162(h0, h1);
            ((__nv_bfloat162*)g_Kh)[idx * 2 + 1] = __nv_bfloat162(h2, h3);
            ((__nv_bfloat162*)g_Kl)[idx * 2]     = __nv_bfloat162(
                __float2bfloat16(q.x - __bfloat162float(h0)),
                __float2bfloat16(q.y - __bfloat162float(h1)));
            ((__nv_bfloat162*)g_Kl)[idx * 2 + 1] = __nv_bfloat162(
                __float2bfloat16(q.z - __bfloat162float(h2)),
                __float2bfloat16(q.w - __bfloat162float(h3)));
        }
    }
}

// ---------------- K2: HMMA (mma.sync bf16) score GEMM, 3-stage pipeline --------
// Tile BM=128 x BN=128, BK=64 bf16. Stage = 32 KB (16K A + 16K B), 3 stages.
// 12 chunks: 3 passes (Qh,Kh), (Qh,Kl), (Ql,Kh) x 4 K-slices of 64.
#define STAGE_BYTES 32768
#define SM_SCORE_TOTAL (3 * STAGE_BYTES)
#define NCHUNK 12

__device__ __forceinline__ void issue_chunk(uint32_t sb, int c, int stage,
                                            int row0, int col0, int tid)
{
    const int p = c >> 2;
    const __nv_bfloat16* __restrict__ A = (p == 2) ? g_Ql : g_Qh;
    const __nv_bfloat16* __restrict__ B = (p == 1) ? g_Kl : g_Kh;
    const int kb = (c & 3) * 128;
    const uint32_t da = sb + stage * STAGE_BYTES;
    const uint32_t db = da + 16384;

    #pragma unroll
    for (int i = 0; i < 4; i++) {
        int f = tid + i * 256;
        int row = f >> 3;
        int chk = (f & 7) * 16;
        uint32_t off = SW128((uint32_t)(row * 128 + chk));
        const char* ga = (const char*)(A + (size_t)(row0 + row) * DDIM) + kb + chk;
        CP_ASYNC16(da + off, ga);
        const char* gb = (const char*)(B + (size_t)(col0 + row) * DDIM) + kb + chk;
        CP_ASYNC16(db + off, gb);
    }
    CP_COMMIT();
}

__global__ __launch_bounds__(256)
void score_mma_kernel(const float* __restrict__ temp)
{
    extern __shared__ char smem[];
    const uint32_t sb = smem_u32(smem);
    const int tid = threadIdx.x, lane = tid & 31, wid = tid >> 5;
    const int wm = wid & 3, wn = wid >> 2;
    const int row0 = blockIdx.y * 128, col0 = blockIdx.x * 128;

    float acc[2][8][4];
    #pragma unroll
    for (int i = 0; i < 2; i++)
        #pragma unroll
        for (int j = 0; j < 8; j++)
            #pragma unroll
            for (int q = 0; q < 4; q++) acc[i][j][q] = 0.f;

    // prologue: stages 0,1 in flight
    issue_chunk(sb, 0, 0, row0, col0, tid);
    issue_chunk(sb, 1, 1, row0, col0, tid);

    for (int c = 0; c < NCHUNK; c++) {
        CP_WAIT(1);                 // chunk c resident (chunk c+1 may be pending)
        __syncthreads();            // visible to all; buffer (c-1)%3 fully consumed

        if (c + 2 < NCHUNK)
            issue_chunk(sb, c + 2, (c + 2) % 3, row0, col0, tid);

        const uint32_t ab = sb + (c % 3) * STAGE_BYTES;
        const uint32_t bb = ab + 16384;

        #pragma unroll
        for (int ks = 0; ks < 4; ks++) {
            uint32_t ar[2][4], br[4][4];
            #pragma unroll
            for (int mt = 0; mt < 2; mt++) {
                int row = wm * 32 + mt * 16 + (lane & 15);
                int kby = ks * 32 + ((lane >> 4) << 4);
                uint32_t addr = ab + SW128((uint32_t)(row * 128 + kby));
                LDSM_X4(ar[mt], addr);
            }
            #pragma unroll
            for (int pt = 0; pt < 4; pt++) {
                int n   = wn * 64 + pt * 16 + (lane & 7) + ((lane >> 4) << 3);
                int kby = ks * 32 + (((lane >> 3) & 1) << 4);
                uint32_t addr = bb + SW128((uint32_t)(n * 128 + kby));
                LDSM_X4(br[pt], addr);
            }
            #pragma unroll
            for (int mt = 0; mt < 2; mt++)
                #pragma unroll
                for (int pt = 0; pt < 4; pt++) {
                    MMA16816(acc[mt][2 * pt],     ar[mt], br[pt][0], br[pt][1]);
                    MMA16816(acc[mt][2 * pt + 1], ar[mt], br[pt][2], br[pt][3]);
                }
        }
        // no trailing sync: next iteration's syncthreads protects buffer reuse
    }

    const float scale = 1.0f / (__ldg(temp) * 16.0f);
    #pragma unroll
    for (int mt = 0; mt < 2; mt++) {
        const int r0g = row0 + wm * 32 + mt * 16 + (lane >> 2);
        const int r1g = r0g + 8;
        #pragma unroll
        for (int nt = 0; nt < 8; nt++) {
            const int gc = col0 + wn * 64 + nt * 8 + (lane & 3) * 2;
            float2 v0, v1;
            v0.x = (r0g == gc)     ? kNEG : acc[mt][nt][0] * scale;
            v0.y = (r0g == gc + 1) ? kNEG : acc[mt][nt][1] * scale;
            v1.x = (r1g == gc)     ? kNEG : acc[mt][nt][2] * scale;
            v1.y = (r1g == gc + 1) ? kNEG : acc[mt][nt][3] * scale;
            *(float2*)&g_S[(size_t)r0g * NROWS + gc] = v0;
            *(float2*)&g_S[(size_t)r1g * NROWS + gc] = v1;
        }
    }
}

// ---------------- K3: top-64 with certified selection ----------------
__global__ __launch_bounds__(256)
void topk_kernel(const float* __restrict__ temp)
{
    const int row = blockIdx.x;
    const int tid = threadIdx.x;
    const float* __restrict__ srow = g_S + (size_t)row * NROWS;

    unsigned u[32];
    #pragma unroll
    for (int j = 0; j < 32; j++) u[j] = f2u(srow[j * 256 + tid]);

    __shared__ int      red_i[8];
    __shared__ float    red_f[8];
    __shared__ unsigned red_u[8];
    __shared__ unsigned cand[CAND_CAP];
    __shared__ int      ambCol[AMB_CAP];
    __shared__ float    ambVal[AMB_CAP];
    __shared__ unsigned char ambKeep[AMB_CAP];
    __shared__ int      s_ccnt, s_amb, s_total;
    __shared__ int      scan_w[8];
    __shared__ unsigned s_thrBits;

    // row max (approx; softmax shift, cancels)
    unsigned mu = 0;
    #pragma unroll
    for (int j = 0; j < 32; j++) mu = max(mu, u[j]);
    mu = blockMaxU(mu, red_u, tid);
    const float m = u2f(mu);

    // ---- phase A: top-8-bit bisection over all values ----
    unsigned prefix = 0;
    for (int bit = 31; bit >= 24; bit--) {
        unsigned t = prefix | (1u << bit);
        int c = 0;
        #pragma unroll
        for (int j = 0; j < 32; j++) c += (u[j] >= t);
        if (blockSumI(c, red_i, tid) >= KSEL) prefix = t;
    }
    const unsigned P = prefix >> 24;

    int ch = 0;
    #pragma unroll
    for (int j = 0; j < 32; j++) ch += ((u[j] >> 24) > P);
    const int c_hi = blockSumI(ch, red_i, tid);
    const int rem = KSEL - c_hi;

    if (tid == 0) s_ccnt = 0;
    __syncthreads();
    #pragma unroll
    for (int j = 0; j < 32; j++) {
        if ((u[j] >> 24) == P) {
            int p = atomicAdd(&s_ccnt, 1);
            if (p < CAND_CAP) cand[p] = u[j];
        }
    }
    __syncthreads();
    const int nc = s_ccnt;

    // ---- phase B: remaining 24 bits ----
    if (nc <= CAND_CAP) {
        // single-warp bisection (warp 0), no block syncs in the loop
        if (tid < 32) {
            unsigned pfx = prefix;
            for (int bit = 23; bit >= 0; bit--) {
                unsigned t = pfx | (1u << bit);
                int c = 0;
                for (int p = tid; p < nc; p += 32) c += (cand[p] >= t);
                #pragma unroll
                for (int o = 16; o; o >>= 1) c += __shfl_down_sync(0xffffffffu, c, o);
                c = __shfl_sync(0xffffffffu, c, 0);
                if (c >= rem) pfx = t;
            }
            if (tid == 0) s_thrBits = pfx;
        }
    } else {
        for (int bit = 23; bit >= 0; bit--) {
            unsigned t = prefix | (1u << bit);
            int c = 0;
            #pragma unroll
            for (int j = 0; j < 32; j++) c += (u[j] >= t);
            if (blockSumI(c, red_i, tid) >= KSEL) prefix = t;
        }
        if (tid == 0) s_thrBits = prefix;
    }
    __syncthreads();
    const unsigned thr = s_thrBits;              // 64th largest approx (bit exact)

    // ---- band classification ----
    const float scale = 1.0f / (__ldg(temp) * 16.0f);
    const float EPS  = 4e-3f * scale;            // >= 2x max approx-score error
    const float s_thr = u2f(thr);
    const float hiB = s_thr + EPS, loB = s_thr - EPS;

    if (tid == 0) s_amb = 0;
    __syncthreads();
    int nhi_loc = 0;
    #pragma unroll
    for (int j = 0; j < 32; j++) {
        float s = u2f(u[j]);
        if (s > hiB) nhi_loc++;
        else if (s >= loB) {
            int p = atomicAdd(&s_amb, 1);
            if (p < AMB_CAP) ambCol[p] = j * 256 + tid;
        }
    }
    const int n_hi = blockSumI(nhi_loc, red_i, tid);
    const int n_amb = min(s_amb, AMB_CAP);
    const int slots = KSEL - n_hi;
    const bool slow = (n_amb != slots);          // block-uniform

    if (slow) {
        const float* __restrict__ qrow = g_Q + (size_t)row * DDIM;
        const int wd = tid >> 5, lane = tid & 31;
        for (int i = wd; i < n_amb; i += 8) {
            const float* __restrict__ krow = g_K + (size_t)ambCol[i] * DDIM;
            float part = 0.f;
            const int e0 = lane * 8;
            #pragma unroll
            for (int e = 0; e < 8; e += 4) {
                float4 qa = *(const float4*)(qrow + e0 + e);
                float4 ka = *(const float4*)(krow + e0 + e);
                part += qa.x * ka.x + qa.y * ka.y + qa.z * ka.z + qa.w * ka.w;
            }
            #pragma unroll
            for (int o = 16; o; o >>= 1) part += __shfl_down_sync(0xffffffffu, part, o);
            if (lane == 0) ambVal[i] = part * scale;
        }
        __syncthreads();
        if (tid < n_amb) {
            float v = ambVal[tid];
            int cg = 0;
            for (int i = 0; i < n_amb; i++) cg += (ambVal[i] > v);
            ambKeep[tid] = (cg < slots) ? 1 : 0;  // keeps >=-threshold ties
        }
        __syncthreads();
    }

    // ---- per-thread kept decisions (deterministic) ----
    unsigned keepMask = 0;
    int myCnt = 0;
    float lsum = 0.f;
    #pragma unroll
    for (int j = 0; j < 32; j++) {
        float s = u2f(u[j]);
        bool kp;
        if (s > hiB) kp = true;
        else if (s >= loB) {
            if (!slow) kp = true;
            else {
                kp = false;
                const int mycol = j * 256 + tid;
                for (int i = 0; i < n_amb; i++)
                    if (ambCol[i] == mycol) { kp = (ambKeep[i] != 0); break; }
            }
        } else kp = false;
        if (kp) { keepMask |= (1u << j); myCnt++; lsum += expf(s - m); }
    }

    // ---- block exclusive scan of myCnt for deterministic slots ----
    {
        const int lane = tid & 31, wd = tid >> 5;
        int sc = myCnt;
        #pragma unroll
        for (int o = 1; o < 32; o <<= 1) {
            int t = __shfl_up_sync(0xffffffffu, sc, o);
            if (lane >= o) sc += t;
        }
        if (lane == 31) scan_w[wd] = sc;
        __syncthreads();
        if (tid == 0) {
            int acc0 = 0;
            for (int i = 0; i < 8; i++) { int t = scan_w[i]; scan_w[i] = acc0; acc0 += t; }
            s_total = acc0;
        }
        __syncthreads();
        int base = scan_w[wd] + sc - myCnt;

        int slot = base;
        #pragma unroll
        for (int j = 0; j < 32; j++) {
            if (keepMask & (1u << j)) {
                if (slot < SLOT_CAP) {
                    g_idx[(size_t)row * SLOT_CAP + slot] = j * 256 + tid;
                    g_e[(size_t)row * SLOT_CAP + slot]   = expf(u2f(u[j]) - m);
                }
                slot++;
            }
        }
    }

    float tot = blockSumF(lsum, red_f, tid);
    if (tid == 0) {
        g_sum[row] = tot;
        g_cnt[row] = min(s_total, SLOT_CAP);
    }
}

// ---------------- K4: out[row] = (sum_j e_j * V[idx_j]) / sum ----------------
__global__ __launch_bounds__(256)
void out_kernel(float* __restrict__ out)
{
    const int row = blockIdx.x;
    const int tid = threadIdx.x;
    __shared__ int   sidx[SLOT_CAP];
    __shared__ float se[SLOT_CAP];
    const int cnt = g_cnt[row];
    if (tid < SLOT_CAP) {
        sidx[tid] = g_idx[(size_t)row * SLOT_CAP + tid];
        se[tid]   = g_e[(size_t)row * SLOT_CAP + tid];
    }
    __syncthreads();
    const float inv = 1.0f / g_sum[row];

    float a0 = 0.f, a1 = 0.f, a2 = 0.f, a3 = 0.f;
    int j = 0;
    for (; j + 4 <= cnt; j += 4) {
        a0 += se[j + 0] * g_V[(size_t)sidx[j + 0] * DDIM + tid];
        a1 += se[j + 1] * g_V[(size_t)sidx[j + 1] * DDIM + tid];
        a2 += se[j + 2] * g_V[(size_t)sidx[j + 2] * DDIM + tid];
        a3 += se[j + 3] * g_V[(size_t)sidx[j + 3] * DDIM + tid];
    }
    for (; j < cnt; j++) a0 += se[j] * g_V[(size_t)sidx[j] * DDIM + tid];

    out[(size_t)row * DDIM + tid] = (a0 + a1 + a2 + a3) * inv;
}

// ---------------- launch ----------------
extern "C" void kernel_launch(void* const* d_in, const int* in_sizes, int n_in,
                              void* d_out, int out_size)
{
    const float* X    = (const float*)d_in[0];
    const float* Wq   = (const float*)d_in[1];
    const float* bq   = (const float*)d_in[2];
    const float* Wk   = (const float*)d_in[3];
    const float* bk   = (const float*)d_in[4];
    const float* Wv   = (const float*)d_in[5];
    const float* bv   = (const float*)d_in[6];
    const float* temp = (const float*)d_in[7];
    float* out = (float*)d_out;

    cudaFuncSetAttribute(score_mma_kernel,
                         cudaFuncAttributeMaxDynamicSharedMemorySize, SM_SCORE_TOTAL);

    dim3 blk(256);
    dim3 gQKV(DDIM / 128, NROWS / 128);
    qkv_kernel<<<gQKV, blk>>>(X, Wq, bq, 0);
    qkv_kernel<<<gQKV, blk>>>(X, Wk, bk, 1);
    qkv_kernel<<<gQKV, blk>>>(X, Wv, bv, 2);

    split_kernel<<<512, 256>>>();

    dim3 gS(NROWS / 128, NROWS / 128);
    score_mma_kernel<<<gS, blk, SM_SCORE_TOTAL>>>(temp);

    topk_kernel<<<NROWS, blk>>>(temp);
    out_kernel<<<NROWS, blk>>>(out);
}

// round 7
// speedup vs baseline: 1.0068x; 1.0001x over previous
#include <cuda_runtime.h>
#include <cuda_bf16.h>
#include <cstdint>

#define NROWS 8192
#define DDIM  256
#define KSEL  64
#define SLOT_CAP 128
#define CAND_CAP 1024
#define AMB_CAP  64

__device__ __constant__ float kNEG = -1.0e9f;

// ---------------- scratch (static device globals; no runtime alloc) -------------
__device__ float g_Q[(size_t)NROWS * DDIM];
__device__ float g_K[(size_t)NROWS * DDIM];
__device__ float g_V[(size_t)NROWS * DDIM];
__device__ float g_S[(size_t)NROWS * NROWS];          // 256 MB score matrix
__device__ __align__(16) __nv_bfloat16 g_Qh[(size_t)NROWS * DDIM];
__device__ __align__(16) __nv_bfloat16 g_Ql[(size_t)NROWS * DDIM];
__device__ __align__(16) __nv_bfloat16 g_Kh[(size_t)NROWS * DDIM];
__device__ __align__(16) __nv_bfloat16 g_Kl[(size_t)NROWS * DDIM];
__device__ int   g_idx[(size_t)NROWS * SLOT_CAP];
__device__ float g_e[(size_t)NROWS * SLOT_CAP];
__device__ int   g_cnt[NROWS];
__device__ float g_sum[NROWS];

// ---------------- generic helpers ----------------
typedef unsigned long long ull;

__device__ __forceinline__ ull pack2(float lo, float hi) {
    ull r;
    asm("mov.b64 %0, {%1, %2};" : "=l"(r) : "r"(__float_as_uint(lo)), "r"(__float_as_uint(hi)));
    return r;
}
__device__ __forceinline__ void unpack2(float& lo, float& hi, ull v) {
    unsigned a, b;
    asm("mov.b64 {%0, %1}, %2;" : "=r"(a), "=r"(b) : "l"(v));
    lo = __uint_as_float(a); hi = __uint_as_float(b);
}
__device__ __forceinline__ void fma2(ull& d, ull a, ull b) {
    asm("fma.rn.f32x2 %0, %1, %2, %3;" : "=l"(d) : "l"(a), "l"(b), "l"(d));
}
__device__ __forceinline__ unsigned f2u(float f) {
    unsigned b = __float_as_uint(f);
    return (b & 0x80000000u) ? ~b : (b | 0x80000000u);
}
__device__ __forceinline__ float u2f(unsigned x) {
    unsigned b = (x & 0x80000000u) ? (x ^ 0x80000000u) : ~x;
    return __uint_as_float(b);
}
__device__ __forceinline__ uint32_t smem_u32(const void* p) {
    uint32_t a;
    asm("{ .reg .u64 t; cvta.to.shared.u64 t, %1; cvt.u32.u64 %0, t; }" : "=r"(a) : "l"(p));
    return a;
}

// ---------------- baseline-PTX async copy + tensor-core macros ----------------
#define CP_ASYNC16(dst, src) \
    asm volatile("cp.async.cg.shared.global [%0], [%1], 16;" :: "r"(dst), "l"(src) : "memory")
#define CP_COMMIT() asm volatile("cp.async.commit_group;" ::: "memory")
#define CP_WAIT(n)  asm volatile("cp.async.wait_group %0;" :: "n"(n) : "memory")

#define LDSM_X4(r, addr) \
    asm volatile("ldmatrix.sync.aligned.m8n8.x4.shared.b16 {%0,%1,%2,%3}, [%4];" \
        : "=r"((r)[0]), "=r"((r)[1]), "=r"((r)[2]), "=r"((r)[3]) : "r"(addr))

#define MMA16816(d, a, b0, b1) \
    asm volatile("mma.sync.aligned.m16n8k16.row.col.f32.bf16.bf16.f32 " \
        "{%0,%1,%2,%3}, {%4,%5,%6,%7}, {%8,%9}, {%0,%1,%2,%3};" \
        : "+f"((d)[0]), "+f"((d)[1]), "+f"((d)[2]), "+f"((d)[3]) \
        : "r"((a)[0]), "r"((a)[1]), "r"((a)[2]), "r"((a)[3]), "r"(b0), "r"(b1))

#define SW128(off) ((off) ^ (((off) >> 3) & 0x70))

// ---------------- block reductions (256 threads, 8 warps) ----------------
__device__ __forceinline__ int blockSumI(int v, int* buf, int tid) {
    #pragma unroll
    for (int o = 16; o; o >>= 1) v += __shfl_down_sync(0xffffffffu, v, o);
    if ((tid & 31) == 0) buf[tid >> 5] = v;
    __syncthreads();
    if (tid < 32) {
        int t = (tid < 8) ? buf[tid] : 0;
        #pragma unroll
        for (int o = 4; o; o >>= 1) t += __shfl_down_sync(0xffffffffu, t, o);
        if (tid == 0) buf[0] = t;
    }
    __syncthreads();
    int r = buf[0];
    __syncthreads();
    return r;
}
__device__ __forceinline__ float blockSumF(float v, float* buf, int tid) {
    #pragma unroll
    for (int o = 16; o; o >>= 1) v += __shfl_down_sync(0xffffffffu, v, o);
    if ((tid & 31) == 0) buf[tid >> 5] = v;
    __syncthreads();
    if (tid < 32) {
        float t = (tid < 8) ? buf[tid] : 0.f;
        #pragma unroll
        for (int o = 4; o; o >>= 1) t += __shfl_down_sync(0xffffffffu, t, o);
        if (tid == 0) buf[0] = t;
    }
    __syncthreads();
    float r = buf[0];
    __syncthreads();
    return r;
}
__device__ __forceinline__ unsigned blockMaxU(unsigned v, unsigned* buf, int tid) {
    #pragma unroll
    for (int o = 16; o; o >>= 1) v = max(v, __shfl_down_sync(0xffffffffu, v, o));
    if ((tid & 31) == 0) buf[tid >> 5] = v;
    __syncthreads();
    if (tid < 32) {
        unsigned t = (tid < 8) ? buf[tid] : 0u;
        #pragma unroll
        for (int o = 4; o; o >>= 1) t = max(t, __shfl_down_sync(0xffffffffu, t, o));
        if (tid == 0) buf[0] = t;
    }
    __syncthreads();
    unsigned r = buf[0];
    __syncthreads();
    return r;
}

// ---------------- FFMA NT-GEMM tile core (for QKV; 128x128, BK=16) --------------
__device__ __forceinline__ void gemm_tile_nt(
    const float* __restrict__ A, const float* __restrict__ B,
    int Kd, int row0, int col0,
    float (*As)[128], float (*Bs)[128], ull acc[8][4])
{
    const int tid = threadIdx.x;
    const int tx = tid & 15, ty = tid >> 4;

    for (int kc = 0; kc < Kd; kc += 16) {
        #pragma unroll
        for (int l = 0; l < 2; l++) {
            int flat = tid + (l << 8);
            int r  = flat >> 2;
            int kq = (flat & 3) << 2;
            float4 va = *(const float4*)(A + (size_t)(row0 + r) * Kd + kc + kq);
            As[kq + 0][r] = va.x; As[kq + 1][r] = va.y;
            As[kq + 2][r] = va.z; As[kq + 3][r] = va.w;
            float4 vb = *(const float4*)(B + (size_t)(col0 + r) * Kd + kc + kq);
            Bs[kq + 0][r] = vb.x; Bs[kq + 1][r] = vb.y;
            Bs[kq + 2][r] = vb.z; Bs[kq + 3][r] = vb.w;
        }
        __syncthreads();
        #pragma unroll
        for (int kk = 0; kk < 16; kk++) {
            float4 a0 = *(const float4*)(&As[kk][ty * 4]);
            float4 a1 = *(const float4*)(&As[kk][ty * 4 + 64]);
            float4 b0 = *(const float4*)(&Bs[kk][tx * 4]);
            float4 b1 = *(const float4*)(&Bs[kk][tx * 4 + 64]);
            ull bb0 = pack2(b0.x, b0.y), bb1 = pack2(b0.z, b0.w);
            ull bb2 = pack2(b1.x, b1.y), bb3 = pack2(b1.z, b1.w);
            float av[8] = {a0.x, a0.y, a0.z, a0.w, a1.x, a1.y, a1.z, a1.w};
            #pragma unroll
            for (int i = 0; i < 8; i++) {
                ull aa = pack2(av[i], av[i]);
                fma2(acc[i][0], aa, bb0);
                fma2(acc[i][1], aa, bb1);
                fma2(acc[i][2], aa, bb2);
                fma2(acc[i][3], aa, bb3);
            }
        }
        __syncthreads();
    }
}

// ---------------- K1: QKV projections (C = X @ W^T + b) ----------------
__global__ __launch_bounds__(256, 2)
void qkv_kernel(const float* __restrict__ X, const float* __restrict__ W,
                const float* __restrict__ bias, int sel)
{
    __shared__ float As[16][128];
    __shared__ float Bs[16][128];
    ull acc[8][4];
    #pragma unroll
    for (int i = 0; i < 8; i++)
        #pragma unroll
        for (int j = 0; j < 4; j++) acc[i][j] = 0ull;

    int row0 = blockIdx.y * 128, col0 = blockIdx.x * 128;
    gemm_tile_nt(X, W, DDIM, row0, col0, As, Bs, acc);

    float* C = (sel == 0) ? g_Q : (sel == 1) ? g_K : g_V;
    const int tid = threadIdx.x, tx = tid & 15, ty = tid >> 4;
    const int gc0 = col0 + tx * 4, gc1 = gc0 + 64;
    float4 b0 = *(const float4*)&bias[gc0];
    float4 b1 = *(const float4*)&bias[gc1];

    #pragma unroll
    for (int i = 0; i < 8; i++) {
        int grow = row0 + ty * 4 + ((i < 4) ? i : 60 + i);
        float o[8];
        unpack2(o[0], o[1], acc[i][0]);
        unpack2(o[2], o[3], acc[i][1]);
        unpack2(o[4], o[5], acc[i][2]);
        unpack2(o[6], o[7], acc[i][3]);
        o[0] += b0.x; o[1] += b0.y; o[2] += b0.z; o[3] += b0.w;
        o[4] += b1.x; o[5] += b1.y; o[6] += b1.z; o[7] += b1.w;
        *(float4*)&C[(size_t)grow * DDIM + gc0] = make_float4(o[0], o[1], o[2], o[3]);
        *(float4*)&C[(size_t)grow * DDIM + gc1] = make_float4(o[4], o[5], o[6], o[7]);
    }
}

// ---------------- K1b: split Q,K into bf16 hi/lo ----------------
__global__ __launch_bounds__(256)
void split_kernel()
{
    const int total = NROWS * DDIM / 4;
    for (int idx = blockIdx.x * blockDim.x + threadIdx.x; idx < total;
         idx += gridDim.x * blockDim.x) {
        {
            float4 q = ((const float4*)g_Q)[idx];
            __nv_bfloat16 h0 = __float2bfloat16(q.x), h1 = __float2bfloat16(q.y);
            __nv_bfloat16 h2 = __float2bfloat16(q.z), h3 = __float2bfloat16(q.w);
            ((__nv_bfloat162*)g_Qh)[idx * 2]     = __nv_bfloat162(h0, h1);
            ((__nv_bfloat162*)g_Qh)[idx * 2 + 1] = __nv_bfloat162(h2, h3);
            ((__nv_bfloat162*)g_Ql)[idx * 2]     = __nv_bfloat162(
                __float2bfloat16(q.x - __bfloat162float(h0)),
                __float2bfloat16(q.y - __bfloat162float(h1)));
            ((__nv_bfloat162*)g_Ql)[idx * 2 + 1] = __nv_bfloat162(
                __float2bfloat16(q.z - __bfloat162float(h2)),
                __float2bfloat16(q.w - __bfloat162float(h3)));
        }
        {
            float4 q = ((const float4*)g_K)[idx];
            __nv_bfloat16 h0 = __float2bfloat16(q.x), h1 = __float2bfloat16(q.y);
            __nv_bfloat16 h2 = __float2bfloat16(q.z), h3 = __float2bfloat16(q.w);
            ((__nv_bfloat162*)g_Kh)[idx * 2]     = __nv_bfloat162(h0, h1);
            ((__nv_bfloat162*)g_Kh)[idx * 2 + 1] = __nv_bfloat162(h2, h3);
            ((__nv_bfloat162*)g_Kl)[idx * 2]     = __nv_bfloat162(
                __float2bfloat16(q.x - __bfloat162float(h0)),
                __float2bfloat16(q.y - __bfloat162float(h1)));
            ((__nv_bfloat162*)g_Kl)[idx * 2 + 1] = __nv_bfloat162(
                __float2bfloat16(q.z - __bfloat162float(h2)),
                __float2bfloat16(q.w - __bfloat162float(h3)));
        }
    }
}

// ---------------- K2: HMMA (mma.sync bf16) score GEMM, 3-stage pipeline --------
// Tile BM=128 x BN=128, BK=64 bf16. Stage = 32 KB (16K A + 16K B), 3 stages.
// 12 chunks: 3 passes (Qh,Kh), (Qh,Kl), (Ql,Kh) x 4 K-slices of 64.
#define STAGE_BYTES 32768
#define SM_SCORE_TOTAL (3 * STAGE_BYTES)
#define NCHUNK 12

__device__ __forceinline__ void issue_chunk(uint32_t sb, int c, int stage,
                                            int row0, int col0, int tid)
{
    const int p = c >> 2;
    const __nv_bfloat16* __restrict__ A = (p == 2) ? g_Ql : g_Qh;
    const __nv_bfloat16* __restrict__ B = (p == 1) ? g_Kl : g_Kh;
    const int kb = (c & 3) * 128;
    const uint32_t da = sb + stage * STAGE_BYTES;
    const uint32_t db = da + 16384;

    #pragma unroll
    for (int i = 0; i < 4; i++) {
        int f = tid + i * 256;
        int row = f >> 3;
        int chk = (f & 7) * 16;
        uint32_t off = SW128((uint32_t)(row * 128 + chk));
        const char* ga = (const char*)(A + (size_t)(row0 + row) * DDIM) + kb + chk;
        CP_ASYNC16(da + off, ga);
        const char* gb = (const char*)(B + (size_t)(col0 + row) * DDIM) + kb + chk;
        CP_ASYNC16(db + off, gb);
    }
    CP_COMMIT();
}

__global__ __launch_bounds__(256)
void score_mma_kernel(const float* __restrict__ temp)
{
    extern __shared__ char smem[];
    const uint32_t sb = smem_u32(smem);
    const int tid = threadIdx.x, lane = tid & 31, wid = tid >> 5;
    const int wm = wid & 3, wn = wid >> 2;
    const int row0 = blockIdx.y * 128, col0 = blockIdx.x * 128;

    float acc[2][8][4];
    #pragma unroll
    for (int i = 0; i < 2; i++)
        #pragma unroll
        for (int j = 0; j < 8; j++)
            #pragma unroll
            for (int q = 0; q < 4; q++) acc[i][j][q] = 0.f;

    // prologue: stages 0,1 in flight
    issue_chunk(sb, 0, 0, row0, col0, tid);
    issue_chunk(sb, 1, 1, row0, col0, tid);

    for (int c = 0; c < NCHUNK; c++) {
        CP_WAIT(1);                 // chunk c resident (chunk c+1 may be pending)
        __syncthreads();            // visible to all; buffer (c-1)%3 fully consumed

        if (c + 2 < NCHUNK)
            issue_chunk(sb, c + 2, (c + 2) % 3, row0, col0, tid);

        const uint32_t ab = sb + (c % 3) * STAGE_BYTES;
        const uint32_t bb = ab + 16384;

        #pragma unroll
        for (int ks = 0; ks < 4; ks++) {
            uint32_t ar[2][4], br[4][4];
            #pragma unroll
            for (int mt = 0; mt < 2; mt++) {
                int row = wm * 32 + mt * 16 + (lane & 15);
                int kby = ks * 32 + ((lane >> 4) << 4);
                uint32_t addr = ab + SW128((uint32_t)(row * 128 + kby));
                LDSM_X4(ar[mt], addr);
            }
            #pragma unroll
            for (int pt = 0; pt < 4; pt++) {
                int n   = wn * 64 + pt * 16 + (lane & 7) + ((lane >> 4) << 3);
                int kby = ks * 32 + (((lane >> 3) & 1) << 4);
                uint32_t addr = bb + SW128((uint32_t)(n * 128 + kby));
                LDSM_X4(br[pt], addr);
            }
            #pragma unroll
            for (int mt = 0; mt < 2; mt++)
                #pragma unroll
                for (int pt = 0; pt < 4; pt++) {
                    MMA16816(acc[mt][2 * pt],     ar[mt], br[pt][0], br[pt][1]);
                    MMA16816(acc[mt][2 * pt + 1], ar[mt], br[pt][2], br[pt][3]);
                }
        }
        // no trailing sync: next iteration's syncthreads protects buffer reuse
    }

    const float scale = 1.0f / (__ldg(temp) * 16.0f);
    #pragma unroll
    for (int mt = 0; mt < 2; mt++) {
        const int r0g = row0 + wm * 32 + mt * 16 + (lane >> 2);
        const int r1g = r0g + 8;
        #pragma unroll
        for (int nt = 0; nt < 8; nt++) {
            const int gc = col0 + wn * 64 + nt * 8 + (lane & 3) * 2;
            float2 v0, v1;
            v0.x = (r0g == gc)     ? kNEG : acc[mt][nt][0] * scale;
            v0.y = (r0g == gc + 1) ? kNEG : acc[mt][nt][1] * scale;
            v1.x = (r1g == gc)     ? kNEG : acc[mt][nt][2] * scale;
            v1.y = (r1g == gc + 1) ? kNEG : acc[mt][nt][3] * scale;
            *(float2*)&g_S[(size_t)r0g * NROWS + gc] = v0;
            *(float2*)&g_S[(size_t)r1g * NROWS + gc] = v1;
        }
    }
}

// ---------------- K3: top-64 with certified selection ----------------
__global__ __launch_bounds__(256)
void topk_kernel(const float* __restrict__ temp)
{
    const int row = blockIdx.x;
    const int tid = threadIdx.x;
    const float* __restrict__ srow = g_S + (size_t)row * NROWS;

    unsigned u[32];
    #pragma unroll
    for (int j = 0; j < 32; j++) u[j] = f2u(srow[j * 256 + tid]);

    __shared__ int      red_i[8];
    __shared__ float    red_f[8];
    __shared__ unsigned red_u[8];
    __shared__ unsigned cand[CAND_CAP];
    __shared__ int      ambCol[AMB_CAP];
    __shared__ float    ambVal[AMB_CAP];
    __shared__ unsigned char ambKeep[AMB_CAP];
    __shared__ int      s_ccnt, s_amb, s_total;
    __shared__ int      scan_w[8];
    __shared__ unsigned s_thrBits;

    // row max (approx; softmax shift, cancels)
    unsigned mu = 0;
    #pragma unroll
    for (int j = 0; j < 32; j++) mu = max(mu, u[j]);
    mu = blockMaxU(mu, red_u, tid);
    const float m = u2f(mu);

    // ---- phase A: top-8-bit bisection over all values ----
    unsigned prefix = 0;
    for (int bit = 31; bit >= 24; bit--) {
        unsigned t = prefix | (1u << bit);
        int c = 0;
        #pragma unroll
        for (int j = 0; j < 32; j++) c += (u[j] >= t);
        if (blockSumI(c, red_i, tid) >= KSEL) prefix = t;
    }
    const unsigned P = prefix >> 24;

    int ch = 0;
    #pragma unroll
    for (int j = 0; j < 32; j++) ch += ((u[j] >> 24) > P);
    const int c_hi = blockSumI(ch, red_i, tid);
    const int rem = KSEL - c_hi;

    if (tid == 0) s_ccnt = 0;
    __syncthreads();
    #pragma unroll
    for (int j = 0; j < 32; j++) {
        if ((u[j] >> 24) == P) {
            int p = atomicAdd(&s_ccnt, 1);
            if (p < CAND_CAP) cand[p] = u[j];
        }
    }
    __syncthreads();
    const int nc = s_ccnt;

    // ---- phase B: remaining 24 bits ----
    if (nc <= CAND_CAP) {
        // single-warp bisection (warp 0), no block syncs in the loop
        if (tid < 32) {
            unsigned pfx = prefix;
            for (int bit = 23; bit >= 0; bit--) {
                unsigned t = pfx | (1u << bit);
                int c = 0;
                for (int p = tid; p < nc; p += 32) c += (cand[p] >= t);
                #pragma unroll
                for (int o = 16; o; o >>= 1) c += __shfl_down_sync(0xffffffffu, c, o);
                c = __shfl_sync(0xffffffffu, c, 0);
                if (c >= rem) pfx = t;
            }
            if (tid == 0) s_thrBits = pfx;
        }
    } else {
        for (int bit = 23; bit >= 0; bit--) {
            unsigned t = prefix | (1u << bit);
            int c = 0;
            #pragma unroll
            for (int j = 0; j < 32; j++) c += (u[j] >= t);
            if (blockSumI(c, red_i, tid) >= KSEL) prefix = t;
        }
        if (tid == 0) s_thrBits = prefix;
    }
    __syncthreads();
    const unsigned thr = s_thrBits;              // 64th largest approx (bit exact)

    // ---- band classification ----
    const float scale = 1.0f / (__ldg(temp) * 16.0f);
    const float EPS  = 4e-3f * scale;            // >= 2x max approx-score error
    const float s_thr = u2f(thr);
    const float hiB = s_thr + EPS, loB = s_thr - EPS;

    if (tid == 0) s_amb = 0;
    __syncthreads();
    int nhi_loc = 0;
    #pragma unroll
    for (int j = 0; j < 32; j++) {
        float s = u2f(u[j]);
        if (s > hiB) nhi_loc++;
        else if (s >= loB) {
            int p = atomicAdd(&s_amb, 1);
            if (p < AMB_CAP) ambCol[p] = j * 256 + tid;
        }
    }
    const int n_hi = blockSumI(nhi_loc, red_i, tid);
    const int n_amb = min(s_amb, AMB_CAP);
    const int slots = KSEL - n_hi;
    const bool slow = (n_amb != slots);          // block-uniform

    if (slow) {
        const float* __restrict__ qrow = g_Q + (size_t)row * DDIM;
        const int wd = tid >> 5, lane = tid & 31;
        for (int i = wd; i < n_amb; i += 8) {
            const float* __restrict__ krow = g_K + (size_t)ambCol[i] * DDIM;
            float part = 0.f;
            const int e0 = lane * 8;
            #pragma unroll
            for (int e = 0; e < 8; e += 4) {
                float4 qa = *(const float4*)(qrow + e0 + e);
                float4 ka = *(const float4*)(krow + e0 + e);
                part += qa.x * ka.x + qa.y * ka.y + qa.z * ka.z + qa.w * ka.w;
            }
            #pragma unroll
            for (int o = 16; o; o >>= 1) part += __shfl_down_sync(0xffffffffu, part, o);
            if (lane == 0) ambVal[i] = part * scale;
        }
        __syncthreads();
        if (tid < n_amb) {
            float v = ambVal[tid];
            int cg = 0;
            for (int i = 0; i < n_amb; i++) cg += (ambVal[i] > v);
            ambKeep[tid] = (cg < slots) ? 1 : 0;  // keeps >=-threshold ties
        }
        __syncthreads();
    }

    // ---- per-thread kept decisions (deterministic) ----
    unsigned keepMask = 0;
    int myCnt = 0;
    float lsum = 0.f;
    #pragma unroll
    for (int j = 0; j < 32; j++) {
        float s = u2f(u[j]);
        bool kp;
        if (s > hiB) kp = true;
        else if (s >= loB) {
            if (!slow) kp = true;
            else {
                kp = false;
                const int mycol = j * 256 + tid;
                for (int i = 0; i < n_amb; i++)
                    if (ambCol[i] == mycol) { kp = (ambKeep[i] != 0); break; }
            }
        } else kp = false;
        if (kp) { keepMask |= (1u << j); myCnt++; lsum += expf(s - m); }
    }

    // ---- block exclusive scan of myCnt for deterministic slots ----
    {
        const int lane = tid & 31, wd = tid >> 5;
        int sc = myCnt;
        #pragma unroll
        for (int o = 1; o < 32; o <<= 1) {
            int t = __shfl_up_sync(0xffffffffu, sc, o);
            if (lane >= o) sc += t;
        }
        if (lane == 31) scan_w[wd] = sc;
        __syncthreads();
        if (tid == 0) {
            int acc0 = 0;
            for (int i = 0; i < 8; i++) { int t = scan_w[i]; scan_w[i] = acc0; acc0 += t; }
            s_total = acc0;
        }
        __syncthreads();
        int base = scan_w[wd] + sc - myCnt;

        int slot = base;
        #pragma unroll
        for (int j = 0; j < 32; j++) {
            if (keepMask & (1u << j)) {
                if (slot < SLOT_CAP) {
                    g_idx[(size_t)row * SLOT_CAP + slot] = j * 256 + tid;
                    g_e[(size_t)row * SLOT_CAP + slot]   = expf(u2f(u[j]) - m);
                }
                slot++;
            }
        }
    }

    float tot = blockSumF(lsum, red_f, tid);
    if (tid == 0) {
        g_sum[row] = tot;
        g_cnt[row] = min(s_total, SLOT_CAP);
    }
}

// ---------------- K4: out[row] = (sum_j e_j * V[idx_j]) / sum ----------------
__global__ __launch_bounds__(256)
void out_kernel(float* __restrict__ out)
{
    const int row = blockIdx.x;
    const int tid = threadIdx.x;
    __shared__ int   sidx[SLOT_CAP];
    __shared__ float se[SLOT_CAP];
    const int cnt = g_cnt[row];
    if (tid < SLOT_CAP) {
        sidx[tid] = g_idx[(size_t)row * SLOT_CAP + tid];
        se[tid]   = g_e[(size_t)row * SLOT_CAP + tid];
    }
    __syncthreads();
    const float inv = 1.0f / g_sum[row];

    float a0 = 0.f, a1 = 0.f, a2 = 0.f, a3 = 0.f;
    int j = 0;
    for (; j + 4 <= cnt; j += 4) {
        a0 += se[j + 0] * g_V[(size_t)sidx[j + 0] * DDIM + tid];
        a1 += se[j + 1] * g_V[(size_t)sidx[j + 1] * DDIM + tid];
        a2 += se[j + 2] * g_V[(size_t)sidx[j + 2] * DDIM + tid];
        a3 += se[j + 3] * g_V[(size_t)sidx[j + 3] * DDIM + tid];
    }
    for (; j < cnt; j++) a0 += se[j] * g_V[(size_t)sidx[j] * DDIM + tid];

    out[(size_t)row * DDIM + tid] = (a0 + a1 + a2 + a3) * inv;
}

// ---------------- launch ----------------
extern "C" void kernel_launch(void* const* d_in, const int* in_sizes, int n_in,
                              void* d_out, int out_size)
{
    const float* X    = (const float*)d_in[0];
    const float* Wq   = (const float*)d_in[1];
    const float* bq   = (const float*)d_in[2];
    const float* Wk   = (const float*)d_in[3];
    const float* bk   = (const float*)d_in[4];
    const float* Wv   = (const float*)d_in[5];
    const float* bv   = (const float*)d_in[6];
    const float* temp = (const float*)d_in[7];
    float* out = (float*)d_out;

    cudaFuncSetAttribute(score_mma_kernel,
                         cudaFuncAttributeMaxDynamicSharedMemorySize, SM_SCORE_TOTAL);

    dim3 blk(256);
    dim3 gQKV(DDIM / 128, NROWS / 128);
    qkv_kernel<<<gQKV, blk>>>(X, Wq, bq, 0);
    qkv_kernel<<<gQKV, blk>>>(X, Wk, bk, 1);
    qkv_kernel<<<gQKV, blk>>>(X, Wv, bv, 2);

    split_kernel<<<512, 256>>>();

    dim3 gS(NROWS / 128, NROWS / 128);
    score_mma_kernel<<<gS, blk, SM_SCORE_TOTAL>>>(temp);

    topk_kernel<<<NROWS, blk>>>(temp);
    out_kernel<<<NROWS, blk>>>(out);
}